// round 13
// baseline (speedup 1.0000x reference)
#include <cuda_runtime.h>

#define N_NODES 50000
#define R_REL 51
#define F_DIM 32
#define E_DIM 32
#define C_DIM 16
#define B_BASES 30
#define NNZ_MAX 2001024
#define CHUNKS 32           // chunks per relation bucket for layer kernels

typedef unsigned long long ull;
typedef unsigned int uint;

// ---- scratch (__device__ globals: no allocation allowed) -------------------
__device__ float g_w1[R_REL * F_DIM * E_DIM];            // [r][f][e]  208 KB
__device__ float g_w2[R_REL * E_DIM * C_DIM];            // [r][h][c]  104 KB
__device__ __align__(16) float g_h1[N_NODES * E_DIM];    // 6.4 MB
__device__ unsigned g_hist[R_REL];
__device__ unsigned g_cursor[R_REL];   // post-scatter: inclusive prefix end of bucket r
__device__ unsigned g_done;
__device__ __align__(16) ull g_meta[NNZ_MAX];            // (v_bits<<32)|(n<<16)|m

// ---- packed f32x2 helpers --------------------------------------------------
__device__ __forceinline__ ull pack2(float lo, float hi) {
    ull r; asm("mov.b64 %0,{%1,%2};" : "=l"(r) : "f"(lo), "f"(hi)); return r;
}
__device__ __forceinline__ void unpack2(ull v, float& lo, float& hi) {
    asm("mov.b64 {%0,%1},%2;" : "=f"(lo), "=f"(hi) : "l"(v));
}
__device__ __forceinline__ ull ffma2(ull a, ull b, ull c) {
    ull d; asm("fma.rn.f32x2 %0,%1,%2,%3;" : "=l"(d) : "l"(a), "l"(b), "l"(c)); return d;
}
__device__ __forceinline__ ull fadd2(ull a, ull b) {
    ull d; asm("add.rn.f32x2 %0,%1,%2;" : "=l"(d) : "l"(a), "l"(b)); return d;
}
__device__ __forceinline__ ull fmul2(ull a, ull b) {
    ull d; asm("mul.rn.f32x2 %0,%1,%2;" : "=l"(d) : "l"(a), "l"(b)); return d;
}
__device__ __forceinline__ void red_add_v2(float* p, float a, float b) {
    asm volatile("red.global.add.v2.f32 [%0], {%1,%2};"
                 :: "l"(p), "f"(a), "f"(b) : "memory");
}
__device__ __forceinline__ ull shfl_xor_u64(ull v, int mask) {
    uint lo = (uint)v, hi = (uint)(v >> 32);
    lo = __shfl_xor_sync(0xffffffffu, lo, mask);
    hi = __shfl_xor_sync(0xffffffffu, hi, mask);
    return ((ull)hi << 32) | lo;
}
__device__ __forceinline__ ulonglong2 ldg_u64x2(const ulonglong2* p) {
    ulonglong2 q;
    asm("ld.global.nc.v2.u64 {%0,%1}, [%2];" : "=l"(q.x), "=l"(q.y) : "l"(p));
    return q;
}

// ---------------------------------------------------------------------------
// Fused: per-relation weights + zero g_hist/g_done + zero g_h1.
// ---------------------------------------------------------------------------
__global__ void compute_w_kernel(const float* __restrict__ comps1,
                                 const float* __restrict__ bases1,
                                 const float* __restrict__ comps2,
                                 const float* __restrict__ bases2) {
    int idx = blockIdx.x * blockDim.x + threadIdx.x;
    const int total1 = R_REL * F_DIM * E_DIM;
    const int total2 = R_REL * E_DIM * C_DIM;
    if (idx < total1) {
        int r = idx / (F_DIM * E_DIM);
        int fe = idx - r * (F_DIM * E_DIM);
        float acc = 0.f;
#pragma unroll
        for (int b = 0; b < B_BASES; b++)
            acc = fmaf(comps1[r * B_BASES + b], bases1[b * (F_DIM * E_DIM) + fe], acc);
        g_w1[idx] = acc;
    }
    if (idx < total2) {
        int r = idx / (E_DIM * C_DIM);
        int hc = idx - r * (E_DIM * C_DIM);
        float acc = 0.f;
#pragma unroll
        for (int b = 0; b < B_BASES; b++)
            acc = fmaf(comps2[r * B_BASES + b], bases2[b * (E_DIM * C_DIM) + hc], acc);
        g_w2[idx] = acc;
    }
    if (idx < R_REL) g_hist[idx] = 0;
    if (idx == 0) g_done = 0;
    float4* h4 = (float4*)g_h1;
    const int nh4 = N_NODES * E_DIM / 4;
    for (int i = idx; i < nh4; i += gridDim.x * blockDim.x)
        h4[i] = make_float4(0.f, 0.f, 0.f, 0.f);
}

// ---------------------------------------------------------------------------
// Fused: histogram + (last block) exclusive-scan -> g_cursor + out = bias2.
// ---------------------------------------------------------------------------
__global__ void hist_kernel(const int* __restrict__ rows, int nnz,
                            float* __restrict__ out,
                            const float* __restrict__ bias2) {
    __shared__ unsigned sh[R_REL];
    if (threadIdx.x < R_REL) sh[threadIdx.x] = 0;
    __syncthreads();
    int gsz = gridDim.x * blockDim.x;
    for (int e = blockIdx.x * blockDim.x + threadIdx.x; e < nnz; e += gsz)
        atomicAdd(&sh[(unsigned)rows[e] / N_NODES], 1u);
    for (int i = blockIdx.x * blockDim.x + threadIdx.x; i < N_NODES * C_DIM; i += gsz)
        out[i] = bias2[i & (C_DIM - 1)];
    __syncthreads();
    if (threadIdx.x < R_REL) atomicAdd(&g_hist[threadIdx.x], sh[threadIdx.x]);
    __threadfence();
    __syncthreads();
    if (threadIdx.x == 0) {
        unsigned t = atomicAdd(&g_done, 1u);
        if (t == gridDim.x - 1) {
            unsigned s = 0;
            for (int r = 0; r < R_REL; r++) { g_cursor[r] = s; s += g_hist[r]; }
        }
    }
}

// Block-aggregated scatter into relation buckets.
// After this kernel, g_cursor[r] == end offset of bucket r (prefix-inclusive).
#define SCATTER_CHUNK 8192
__global__ void scatter_kernel(const int* __restrict__ rows,
                               const int* __restrict__ cols,
                               const float* __restrict__ vals, int nnz) {
    __shared__ unsigned cnt[R_REL];
    __shared__ unsigned base[R_REL];
    int start = blockIdx.x * SCATTER_CHUNK;
    if (start >= nnz) return;
    int end = min(start + SCATTER_CHUNK, nnz);

    if (threadIdx.x < R_REL) cnt[threadIdx.x] = 0;
    __syncthreads();
    for (int e = start + threadIdx.x; e < end; e += blockDim.x)
        atomicAdd(&cnt[(unsigned)rows[e] / N_NODES], 1u);
    __syncthreads();
    if (threadIdx.x < R_REL) {
        base[threadIdx.x] = atomicAdd(&g_cursor[threadIdx.x], cnt[threadIdx.x]);
        cnt[threadIdx.x] = 0;
    }
    __syncthreads();
    for (int e = start + threadIdx.x; e < end; e += blockDim.x) {
        unsigned row = (unsigned)rows[e];
        unsigned r = row / N_NODES;
        unsigned n = row - r * N_NODES;
        unsigned pos = base[r] + atomicAdd(&cnt[r], 1u);
        g_meta[pos] = ((ull)__float_as_uint(vals[e]) << 32)
                    | (n << 16) | (unsigned)cols[e];
    }
}

__global__ void relu_bias_kernel(const float* __restrict__ bias1) {
    int idx = blockIdx.x * blockDim.x + threadIdx.x;
    const int n4 = N_NODES * E_DIM / 4;
    if (idx < n4) {
        float4* h4 = (float4*)g_h1;
        const float4* b4 = (const float4*)bias1;
        float4 v = h4[idx];
        float4 b = b4[idx & (E_DIM / 4 - 1)];
        v.x = fmaxf(v.x + b.x, 0.f);
        v.y = fmaxf(v.y + b.y, 0.f);
        v.z = fmaxf(v.z + b.z, 0.f);
        v.w = fmaxf(v.w + b.w, 0.f);
        h4[idx] = v;
    }
}

// ---------------------------------------------------------------------------
// Layer 1: CTA = (relation, chunk); register weights; warp-per-edge.
// fi = lane>>4 (f-half), ep = lane&15 (e-pair: e0=2ep, e1=2ep+1).
// f32x2 halves carry (f even, f odd) partials to the SAME e (pack-free math).
// FULL double buffer: meta prefetched 2 ahead, entire x half-row 1 ahead.
// Every x operand has load->use distance of one full iteration.
// ---------------------------------------------------------------------------
__global__ __launch_bounds__(256, 3)
void layer1_kernel(const float* __restrict__ x) {
    const unsigned r     = blockIdx.x / CHUNKS;
    const unsigned chunk = blockIdx.x % CHUNKS;
    const unsigned lo  = (r == 0) ? 0u : g_cursor[r - 1];
    const unsigned hi  = g_cursor[r];
    const unsigned len = hi - lo;
    const unsigned cstart = lo + (unsigned)(((ull)len * chunk) / CHUNKS);
    const unsigned cend   = lo + (unsigned)(((ull)len * (chunk + 1)) / CHUNKS);

    const int lane = threadIdx.x & 31;
    const int wid  = threadIdx.x >> 5;            // 8 warps / CTA
    const int fi   = lane >> 4;                   // 0/1 (f half)
    const int ep   = lane & 15;                   // e-pair index

    // Pre-pack weights across f (one-time).
    const float* wr = g_w1 + r * (F_DIM * E_DIM) + (fi * 16) * E_DIM;
    ull wA[8], wB[8];
#pragma unroll
    for (int k = 0; k < 8; k++) {
        wA[k] = pack2(wr[(2 * k) * E_DIM + 2 * ep],
                      wr[(2 * k + 1) * E_DIM + 2 * ep]);
        wB[k] = pack2(wr[(2 * k) * E_DIM + 2 * ep + 1],
                      wr[(2 * k + 1) * E_DIM + 2 * ep + 1]);
    }

    unsigned e0 = cstart + wid;
    if (e0 >= cend) return;
    const unsigned last = cend - 1;

    // prologue: meta for e0, e1; full half-row for e0
    unsigned e1 = e0 + 8;
    ull meta0 = g_meta[e0];
    ull meta1 = g_meta[e1 < cend ? e1 : last];

    const ulonglong2* xp =
        (const ulonglong2*)(x + (size_t)(meta0 & 0xFFFFu) * F_DIM + fi * 16);
    ulonglong2 c0 = ldg_u64x2(xp), c1 = ldg_u64x2(xp + 1);
    ulonglong2 c2 = ldg_u64x2(xp + 2), c3 = ldg_u64x2(xp + 3);

    while (e0 < cend) {
        // meta prefetch (depth 2)
        unsigned e2 = e1 + 8;
        ull meta2 = g_meta[e2 < cend ? e2 : last];
        // full row prefetch for e1 (depth 1)
        const ulonglong2* xn =
            (const ulonglong2*)(x + (size_t)(meta1 & 0xFFFFu) * F_DIM + fi * 16);
        ulonglong2 n0 = ldg_u64x2(xn),     n1 = ldg_u64x2(xn + 1);
        ulonglong2 n2 = ldg_u64x2(xn + 2), n3 = ldg_u64x2(xn + 3);

        ull accA = 0, accB = 0;       // halves = (f-even, f-odd) partials
        accA = ffma2(c0.x, wA[0], accA);  accB = ffma2(c0.x, wB[0], accB);
        accA = ffma2(c0.y, wA[1], accA);  accB = ffma2(c0.y, wB[1], accB);
        accA = ffma2(c1.x, wA[2], accA);  accB = ffma2(c1.x, wB[2], accB);
        accA = ffma2(c1.y, wA[3], accA);  accB = ffma2(c1.y, wB[3], accB);
        accA = ffma2(c2.x, wA[4], accA);  accB = ffma2(c2.x, wB[4], accB);
        accA = ffma2(c2.y, wA[5], accA);  accB = ffma2(c2.y, wB[5], accB);
        accA = ffma2(c3.x, wA[6], accA);  accB = ffma2(c3.x, wB[6], accB);
        accA = ffma2(c3.y, wA[7], accA);  accB = ffma2(c3.y, wB[7], accB);

        float aLo, aHi, bLo, bHi;
        unpack2(accA, aLo, aHi);
        unpack2(accB, bLo, bHi);
        ull p = pack2(aLo + aHi, bLo + bHi);      // (e0, e1) partial for this fi
        p = fadd2(p, shfl_xor_u64(p, 16));        // reduce over fi
        if (fi == 0) {
            float v0 = __uint_as_float((uint)(meta0 >> 32));
            float o0, o1;
            unpack2(fmul2(p, pack2(v0, v0)), o0, o1);
            red_add_v2(g_h1 + (size_t)((meta0 >> 16) & 0xFFFFu) * E_DIM + ep * 2,
                       o0, o1);
        }
        // shift pipeline
        e0 = e1; e1 = e2;
        meta0 = meta1; meta1 = meta2;
        c0 = n0; c1 = n1; c2 = n2; c3 = n3;
    }
}

// ---------------------------------------------------------------------------
// Layer 2: 2 edges per warp (16 lanes each): half = lane>>4 picks edge.
// fi = (lane>>3)&1 (f-half), cp = lane&7 (c-pair: c0=2cp, c1=2cp+1).
// Same pack-free math + full double buffer; shfl_xor(8) reduce; red.v2 scatter.
// ---------------------------------------------------------------------------
__global__ __launch_bounds__(256, 3)
void layer2_kernel(float* __restrict__ out) {
    const unsigned r     = blockIdx.x / CHUNKS;
    const unsigned chunk = blockIdx.x % CHUNKS;
    const unsigned lo  = (r == 0) ? 0u : g_cursor[r - 1];
    const unsigned hi  = g_cursor[r];
    const unsigned len = hi - lo;
    const unsigned cstart = lo + (unsigned)(((ull)len * chunk) / CHUNKS);
    const unsigned cend   = lo + (unsigned)(((ull)len * (chunk + 1)) / CHUNKS);

    const int lane = threadIdx.x & 31;
    const int wid  = threadIdx.x >> 5;
    const int half = lane >> 4;                   // which edge of the pair
    const int fi   = (lane >> 3) & 1;             // f half
    const int cp   = lane & 7;                    // c-pair index

    const float* wr = g_w2 + r * (E_DIM * C_DIM) + (fi * 16) * C_DIM;
    ull wA[8], wB[8];
#pragma unroll
    for (int k = 0; k < 8; k++) {
        wA[k] = pack2(wr[(2 * k) * C_DIM + 2 * cp],
                      wr[(2 * k + 1) * C_DIM + 2 * cp]);
        wB[k] = pack2(wr[(2 * k) * C_DIM + 2 * cp + 1],
                      wr[(2 * k + 1) * C_DIM + 2 * cp + 1]);
    }

    unsigned b0 = cstart + wid * 2;
    if (b0 >= cend) return;
    const unsigned last = cend - 1;

    // prologue (invalid edge -> clamp index, v forced to 0)
    unsigned eI0 = b0 + half;
    ull meta0 = g_meta[eI0 < cend ? eI0 : last];
    if (eI0 >= cend) meta0 &= 0xFFFFFFFFull;      // v = 0

    unsigned b1 = b0 + 16;
    unsigned eI1 = b1 + half;
    ull meta1 = g_meta[eI1 < cend ? eI1 : last];
    if (eI1 >= cend) meta1 &= 0xFFFFFFFFull;

    const ulonglong2* hp =
        (const ulonglong2*)(g_h1 + (size_t)(meta0 & 0xFFFFu) * E_DIM + fi * 16);
    ulonglong2 c0 = ldg_u64x2(hp), c1 = ldg_u64x2(hp + 1);
    ulonglong2 c2 = ldg_u64x2(hp + 2), c3 = ldg_u64x2(hp + 3);

    while (b0 < cend) {
        unsigned b2 = b1 + 16;
        unsigned eI2 = b2 + half;
        ull meta2 = g_meta[eI2 < cend ? eI2 : last];
        if (eI2 >= cend) meta2 &= 0xFFFFFFFFull;

        const ulonglong2* hn =
            (const ulonglong2*)(g_h1 + (size_t)(meta1 & 0xFFFFu) * E_DIM + fi * 16);
        ulonglong2 n0 = ldg_u64x2(hn),     n1 = ldg_u64x2(hn + 1);
        ulonglong2 n2 = ldg_u64x2(hn + 2), n3 = ldg_u64x2(hn + 3);

        ull accA = 0, accB = 0;
        accA = ffma2(c0.x, wA[0], accA);  accB = ffma2(c0.x, wB[0], accB);
        accA = ffma2(c0.y, wA[1], accA);  accB = ffma2(c0.y, wB[1], accB);
        accA = ffma2(c1.x, wA[2], accA);  accB = ffma2(c1.x, wB[2], accB);
        accA = ffma2(c1.y, wA[3], accA);  accB = ffma2(c1.y, wB[3], accB);
        accA = ffma2(c2.x, wA[4], accA);  accB = ffma2(c2.x, wB[4], accB);
        accA = ffma2(c2.y, wA[5], accA);  accB = ffma2(c2.y, wB[5], accB);
        accA = ffma2(c3.x, wA[6], accA);  accB = ffma2(c3.x, wB[6], accB);
        accA = ffma2(c3.y, wA[7], accA);  accB = ffma2(c3.y, wB[7], accB);

        float aLo, aHi, bLo, bHi;
        unpack2(accA, aLo, aHi);
        unpack2(accB, bLo, bHi);
        ull p = pack2(aLo + aHi, bLo + bHi);
        p = fadd2(p, shfl_xor_u64(p, 8));
        if (fi == 0) {
            float v0 = __uint_as_float((uint)(meta0 >> 32));
            float o0, o1;
            unpack2(fmul2(p, pack2(v0, v0)), o0, o1);
            red_add_v2(out + (size_t)((meta0 >> 16) & 0xFFFFu) * C_DIM + cp * 2,
                       o0, o1);
        }
        b0 = b1; b1 = b2;
        meta0 = meta1; meta1 = meta2;
        c0 = n0; c1 = n1; c2 = n2; c3 = n3;
    }
}

// ---------------------------------------------------------------------------
extern "C" void kernel_launch(void* const* d_in, const int* in_sizes, int n_in,
                              void* d_out, int out_size) {
    const float* features = (const float*)d_in[0];
    const float* vals     = (const float*)d_in[1];
    const float* comps1   = (const float*)d_in[2];
    const float* bases1   = (const float*)d_in[3];
    const float* bias1    = (const float*)d_in[4];
    const float* comps2   = (const float*)d_in[5];
    const float* bases2   = (const float*)d_in[6];
    const float* bias2    = (const float*)d_in[7];
    const int*   rows     = (const int*)d_in[8];
    const int*   cols     = (const int*)d_in[9];
    float*       out      = (float*)d_out;
    const int    nnz      = in_sizes[8];

    // 1. weights + zero hist/done/h1
    compute_w_kernel<<<512, 256>>>(comps1, bases1, comps2, bases2);
    // 2. histogram + last-block scan + out=bias2
    hist_kernel<<<256, 256>>>(rows, nnz, out, bias2);
    // 3. bucket scatter (relation-sorted edge list; g_cursor -> bucket ends)
    scatter_kernel<<<(nnz + SCATTER_CHUNK - 1) / SCATTER_CHUNK, 512>>>(
        rows, cols, vals, nnz);
    // 4. layer 1 (register weights, full double buffer, pack-free FFMA2)
    layer1_kernel<<<R_REL * CHUNKS, 256>>>(features);
    // 5. bias + relu
    relu_bias_kernel<<<(N_NODES * E_DIM / 4 + 255) / 256, 256>>>(bias1);
    // 6. layer 2
    layer2_kernel<<<R_REL * CHUNKS, 256>>>(out);
}

// round 14
// speedup vs baseline: 1.0286x; 1.0286x over previous
#include <cuda_runtime.h>

#define N_NODES 50000
#define R_REL 51
#define F_DIM 32
#define E_DIM 32
#define C_DIM 16
#define B_BASES 30
#define NNZ_MAX 2001024
#define CHUNKS 32           // chunks per relation bucket for layer kernels

typedef unsigned long long ull;
typedef unsigned int uint;

// ---- scratch (__device__ globals: no allocation allowed) -------------------
__device__ float g_w1[R_REL * F_DIM * E_DIM];            // [r][f][e]  208 KB
__device__ float g_w2[R_REL * E_DIM * C_DIM];            // [r][h][c]  104 KB
__device__ __align__(16) float g_h1[N_NODES * E_DIM];    // 6.4 MB
__device__ unsigned g_hist[R_REL];
__device__ unsigned g_cursor[R_REL];   // post-scatter: inclusive prefix end of bucket r
__device__ unsigned g_done;
__device__ __align__(16) ull g_meta[NNZ_MAX];            // (v_bits<<32)|(n<<16)|m

// ---- packed f32x2 helpers --------------------------------------------------
__device__ __forceinline__ ull pack2(float lo, float hi) {
    ull r; asm("mov.b64 %0,{%1,%2};" : "=l"(r) : "f"(lo), "f"(hi)); return r;
}
__device__ __forceinline__ void unpack2(ull v, float& lo, float& hi) {
    asm("mov.b64 {%0,%1},%2;" : "=f"(lo), "=f"(hi) : "l"(v));
}
__device__ __forceinline__ ull ffma2(ull a, ull b, ull c) {
    ull d; asm("fma.rn.f32x2 %0,%1,%2,%3;" : "=l"(d) : "l"(a), "l"(b), "l"(c)); return d;
}
__device__ __forceinline__ ull fadd2(ull a, ull b) {
    ull d; asm("add.rn.f32x2 %0,%1,%2;" : "=l"(d) : "l"(a), "l"(b)); return d;
}
__device__ __forceinline__ ull fmul2(ull a, ull b) {
    ull d; asm("mul.rn.f32x2 %0,%1,%2;" : "=l"(d) : "l"(a), "l"(b)); return d;
}
__device__ __forceinline__ void red_add_v4(float* p, float a, float b, float c, float d) {
    asm volatile("red.global.add.v4.f32 [%0], {%1,%2,%3,%4};"
                 :: "l"(p), "f"(a), "f"(b), "f"(c), "f"(d) : "memory");
}
__device__ __forceinline__ ull shfl_xor_u64(ull v, int mask) {
    uint lo = (uint)v, hi = (uint)(v >> 32);
    lo = __shfl_xor_sync(0xffffffffu, lo, mask);
    hi = __shfl_xor_sync(0xffffffffu, hi, mask);
    return ((ull)hi << 32) | lo;
}
__device__ __forceinline__ ulonglong2 ldg_u64x2(const ulonglong2* p) {
    ulonglong2 q;
    asm("ld.global.nc.v2.u64 {%0,%1}, [%2];" : "=l"(q.x), "=l"(q.y) : "l"(p));
    return q;
}

// ---------------------------------------------------------------------------
// Fused: per-relation weights + zero g_hist/g_done + zero g_h1.
// ---------------------------------------------------------------------------
__global__ void compute_w_kernel(const float* __restrict__ comps1,
                                 const float* __restrict__ bases1,
                                 const float* __restrict__ comps2,
                                 const float* __restrict__ bases2) {
    int idx = blockIdx.x * blockDim.x + threadIdx.x;
    const int total1 = R_REL * F_DIM * E_DIM;
    const int total2 = R_REL * E_DIM * C_DIM;
    if (idx < total1) {
        int r = idx / (F_DIM * E_DIM);
        int fe = idx - r * (F_DIM * E_DIM);
        float acc = 0.f;
#pragma unroll
        for (int b = 0; b < B_BASES; b++)
            acc = fmaf(comps1[r * B_BASES + b], bases1[b * (F_DIM * E_DIM) + fe], acc);
        g_w1[idx] = acc;
    }
    if (idx < total2) {
        int r = idx / (E_DIM * C_DIM);
        int hc = idx - r * (E_DIM * C_DIM);
        float acc = 0.f;
#pragma unroll
        for (int b = 0; b < B_BASES; b++)
            acc = fmaf(comps2[r * B_BASES + b], bases2[b * (E_DIM * C_DIM) + hc], acc);
        g_w2[idx] = acc;
    }
    if (idx < R_REL) g_hist[idx] = 0;
    if (idx == 0) g_done = 0;
    float4* h4 = (float4*)g_h1;
    const int nh4 = N_NODES * E_DIM / 4;
    for (int i = idx; i < nh4; i += gridDim.x * blockDim.x)
        h4[i] = make_float4(0.f, 0.f, 0.f, 0.f);
}

// ---------------------------------------------------------------------------
// Fused: histogram + (last block) exclusive-scan -> g_cursor + out = bias2.
// ---------------------------------------------------------------------------
__global__ void hist_kernel(const int* __restrict__ rows, int nnz,
                            float* __restrict__ out,
                            const float* __restrict__ bias2) {
    __shared__ unsigned sh[R_REL];
    if (threadIdx.x < R_REL) sh[threadIdx.x] = 0;
    __syncthreads();
    int gsz = gridDim.x * blockDim.x;
    for (int e = blockIdx.x * blockDim.x + threadIdx.x; e < nnz; e += gsz)
        atomicAdd(&sh[(unsigned)rows[e] / N_NODES], 1u);
    for (int i = blockIdx.x * blockDim.x + threadIdx.x; i < N_NODES * C_DIM; i += gsz)
        out[i] = bias2[i & (C_DIM - 1)];
    __syncthreads();
    if (threadIdx.x < R_REL) atomicAdd(&g_hist[threadIdx.x], sh[threadIdx.x]);
    __threadfence();
    __syncthreads();
    if (threadIdx.x == 0) {
        unsigned t = atomicAdd(&g_done, 1u);
        if (t == gridDim.x - 1) {
            unsigned s = 0;
            for (int r = 0; r < R_REL; r++) { g_cursor[r] = s; s += g_hist[r]; }
        }
    }
}

// Block-aggregated scatter into relation buckets.
#define SCATTER_CHUNK 8192
__global__ void scatter_kernel(const int* __restrict__ rows,
                               const int* __restrict__ cols,
                               const float* __restrict__ vals, int nnz) {
    __shared__ unsigned cnt[R_REL];
    __shared__ unsigned base[R_REL];
    int start = blockIdx.x * SCATTER_CHUNK;
    if (start >= nnz) return;
    int end = min(start + SCATTER_CHUNK, nnz);

    if (threadIdx.x < R_REL) cnt[threadIdx.x] = 0;
    __syncthreads();
    for (int e = start + threadIdx.x; e < end; e += blockDim.x)
        atomicAdd(&cnt[(unsigned)rows[e] / N_NODES], 1u);
    __syncthreads();
    if (threadIdx.x < R_REL) {
        base[threadIdx.x] = atomicAdd(&g_cursor[threadIdx.x], cnt[threadIdx.x]);
        cnt[threadIdx.x] = 0;
    }
    __syncthreads();
    for (int e = start + threadIdx.x; e < end; e += blockDim.x) {
        unsigned row = (unsigned)rows[e];
        unsigned r = row / N_NODES;
        unsigned n = row - r * N_NODES;
        unsigned pos = base[r] + atomicAdd(&cnt[r], 1u);
        g_meta[pos] = ((ull)__float_as_uint(vals[e]) << 32)
                    | (n << 16) | (unsigned)cols[e];
    }
}

__global__ void relu_bias_kernel(const float* __restrict__ bias1) {
    int idx = blockIdx.x * blockDim.x + threadIdx.x;
    const int n4 = N_NODES * E_DIM / 4;
    if (idx < n4) {
        float4* h4 = (float4*)g_h1;
        const float4* b4 = (const float4*)bias1;
        float4 v = h4[idx];
        float4 b = b4[idx & (E_DIM / 4 - 1)];
        v.x = fmaxf(v.x + b.x, 0.f);
        v.y = fmaxf(v.y + b.y, 0.f);
        v.z = fmaxf(v.z + b.z, 0.f);
        v.w = fmaxf(v.w + b.w, 0.f);
        h4[idx] = v;
    }
}

// ---------------------------------------------------------------------------
// Layer 1: CTA = (relation, chunk); register weights; warp-per-edge.
// NEW partition: fi = lane>>3 (4 groups x 8 f), eq = lane&7 (e = 4eq..4eq+3).
// Scatter = red.v4 from only 8 lanes (halves REDG lane cost vs v2 x 16).
// x load per lane: 32B slice (2 LDG.128). Reduce over fi: shfl_xor 8, 16.
// f32x2 halves still carry (f even, f odd) partials (pack-free mainloop).
// ---------------------------------------------------------------------------
__global__ __launch_bounds__(256, 3)
void layer1_kernel(const float* __restrict__ x) {
    const unsigned r     = blockIdx.x / CHUNKS;
    const unsigned chunk = blockIdx.x % CHUNKS;
    const unsigned lo  = (r == 0) ? 0u : g_cursor[r - 1];
    const unsigned hi  = g_cursor[r];
    const unsigned len = hi - lo;
    const unsigned cstart = lo + (unsigned)(((ull)len * chunk) / CHUNKS);
    const unsigned cend   = lo + (unsigned)(((ull)len * (chunk + 1)) / CHUNKS);

    const int lane = threadIdx.x & 31;
    const int wid  = threadIdx.x >> 5;            // 8 warps / CTA
    const int fi   = lane >> 3;                   // 0..3 (f-quarter: 8 f each)
    const int eq   = lane & 7;                    // e-quad: e = 4eq..4eq+3

    // Pre-pack weights across f (one-time): 4 f-pairs x 4 outputs = 16 ull.
    const float* wr = g_w1 + r * (F_DIM * E_DIM) + (fi * 8) * E_DIM;
    ull wA[4], wB[4], wC[4], wD[4];
#pragma unroll
    for (int k = 0; k < 4; k++) {
        const float* w0 = wr + (2 * k) * E_DIM + eq * 4;
        const float* w1 = wr + (2 * k + 1) * E_DIM + eq * 4;
        wA[k] = pack2(w0[0], w1[0]);
        wB[k] = pack2(w0[1], w1[1]);
        wC[k] = pack2(w0[2], w1[2]);
        wD[k] = pack2(w0[3], w1[3]);
    }

    unsigned e0 = cstart + wid;
    if (e0 >= cend) return;
    const unsigned last = cend - 1;

    // prologue: meta for e0, e1; x slice for e0
    unsigned e1 = e0 + 8;
    ull meta0 = g_meta[e0];
    ull meta1 = g_meta[e1 < cend ? e1 : last];

    const ulonglong2* xp =
        (const ulonglong2*)(x + (size_t)(meta0 & 0xFFFFu) * F_DIM + fi * 8);
    ulonglong2 c0 = ldg_u64x2(xp), c1 = ldg_u64x2(xp + 1);

    while (e0 < cend) {
        // meta prefetch (depth 2)
        unsigned e2 = e1 + 8;
        ull meta2 = g_meta[e2 < cend ? e2 : last];
        // x slice prefetch for e1 (depth 1)
        const ulonglong2* xn =
            (const ulonglong2*)(x + (size_t)(meta1 & 0xFFFFu) * F_DIM + fi * 8);
        ulonglong2 n0 = ldg_u64x2(xn), n1 = ldg_u64x2(xn + 1);

        ull accA = 0, accB = 0, accC = 0, accD = 0;
        accA = ffma2(c0.x, wA[0], accA);  accB = ffma2(c0.x, wB[0], accB);
        accC = ffma2(c0.x, wC[0], accC);  accD = ffma2(c0.x, wD[0], accD);
        accA = ffma2(c0.y, wA[1], accA);  accB = ffma2(c0.y, wB[1], accB);
        accC = ffma2(c0.y, wC[1], accC);  accD = ffma2(c0.y, wD[1], accD);
        accA = ffma2(c1.x, wA[2], accA);  accB = ffma2(c1.x, wB[2], accB);
        accC = ffma2(c1.x, wC[2], accC);  accD = ffma2(c1.x, wD[2], accD);
        accA = ffma2(c1.y, wA[3], accA);  accB = ffma2(c1.y, wB[3], accB);
        accC = ffma2(c1.y, wC[3], accC);  accD = ffma2(c1.y, wD[3], accD);

        // fold (f-even + f-odd) -> 4 scalars, pack into 2 ull
        float sa0, sa1, sb0, sb1, sc0, sc1, sd0, sd1;
        unpack2(accA, sa0, sa1);  unpack2(accB, sb0, sb1);
        unpack2(accC, sc0, sc1);  unpack2(accD, sd0, sd1);
        ull p01 = pack2(sa0 + sa1, sb0 + sb1);    // (e0, e1)
        ull p23 = pack2(sc0 + sc1, sd0 + sd1);    // (e2, e3)
        // reduce over the 4 fi groups
        p01 = fadd2(p01, shfl_xor_u64(p01, 8));
        p23 = fadd2(p23, shfl_xor_u64(p23, 8));
        p01 = fadd2(p01, shfl_xor_u64(p01, 16));
        p23 = fadd2(p23, shfl_xor_u64(p23, 16));
        if (fi == 0) {                             // 8 lanes per edge
            float v0 = __uint_as_float((uint)(meta0 >> 32));
            ull vp = pack2(v0, v0);
            float o0, o1, o2, o3;
            unpack2(fmul2(p01, vp), o0, o1);
            unpack2(fmul2(p23, vp), o2, o3);
            red_add_v4(g_h1 + (size_t)((meta0 >> 16) & 0xFFFFu) * E_DIM + eq * 4,
                       o0, o1, o2, o3);
        }
        // shift pipeline
        e0 = e1; e1 = e2;
        meta0 = meta1; meta1 = meta2;
        c0 = n0; c1 = n1;
    }
}

// ---------------------------------------------------------------------------
// Layer 2: 2 edges per warp (16 lanes each): half = lane>>4 picks edge.
// Within half: fi = (hl>>2) (4 groups x 8 f), cq = hl&3 (c = 4cq..4cq+3).
// red.v4 from 4 lanes per edge. Reduce over fi: shfl_xor 4, 8.
// ---------------------------------------------------------------------------
__global__ __launch_bounds__(256, 3)
void layer2_kernel(float* __restrict__ out) {
    const unsigned r     = blockIdx.x / CHUNKS;
    const unsigned chunk = blockIdx.x % CHUNKS;
    const unsigned lo  = (r == 0) ? 0u : g_cursor[r - 1];
    const unsigned hi  = g_cursor[r];
    const unsigned len = hi - lo;
    const unsigned cstart = lo + (unsigned)(((ull)len * chunk) / CHUNKS);
    const unsigned cend   = lo + (unsigned)(((ull)len * (chunk + 1)) / CHUNKS);

    const int lane = threadIdx.x & 31;
    const int wid  = threadIdx.x >> 5;
    const int half = lane >> 4;                   // which edge of the pair
    const int hl   = lane & 15;
    const int fi   = hl >> 2;                     // 0..3 (8 f each)
    const int cq   = hl & 3;                      // c-quad: c = 4cq..4cq+3

    const float* wr = g_w2 + r * (E_DIM * C_DIM) + (fi * 8) * C_DIM;
    ull wA[4], wB[4], wC[4], wD[4];
#pragma unroll
    for (int k = 0; k < 4; k++) {
        const float* w0 = wr + (2 * k) * C_DIM + cq * 4;
        const float* w1 = wr + (2 * k + 1) * C_DIM + cq * 4;
        wA[k] = pack2(w0[0], w1[0]);
        wB[k] = pack2(w0[1], w1[1]);
        wC[k] = pack2(w0[2], w1[2]);
        wD[k] = pack2(w0[3], w1[3]);
    }

    unsigned b0 = cstart + wid * 2;
    if (b0 >= cend) return;
    const unsigned last = cend - 1;

    // prologue (invalid edge -> clamp index, v forced to 0)
    unsigned eI0 = b0 + half;
    ull meta0 = g_meta[eI0 < cend ? eI0 : last];
    if (eI0 >= cend) meta0 &= 0xFFFFFFFFull;      // v = 0

    unsigned b1 = b0 + 16;
    unsigned eI1 = b1 + half;
    ull meta1 = g_meta[eI1 < cend ? eI1 : last];
    if (eI1 >= cend) meta1 &= 0xFFFFFFFFull;

    const ulonglong2* hp =
        (const ulonglong2*)(g_h1 + (size_t)(meta0 & 0xFFFFu) * E_DIM + fi * 8);
    ulonglong2 c0 = ldg_u64x2(hp), c1 = ldg_u64x2(hp + 1);

    while (b0 < cend) {
        unsigned b2 = b1 + 16;
        unsigned eI2 = b2 + half;
        ull meta2 = g_meta[eI2 < cend ? eI2 : last];
        if (eI2 >= cend) meta2 &= 0xFFFFFFFFull;

        const ulonglong2* hn =
            (const ulonglong2*)(g_h1 + (size_t)(meta1 & 0xFFFFu) * E_DIM + fi * 8);
        ulonglong2 n0 = ldg_u64x2(hn), n1 = ldg_u64x2(hn + 1);

        ull accA = 0, accB = 0, accC = 0, accD = 0;
        accA = ffma2(c0.x, wA[0], accA);  accB = ffma2(c0.x, wB[0], accB);
        accC = ffma2(c0.x, wC[0], accC);  accD = ffma2(c0.x, wD[0], accD);
        accA = ffma2(c0.y, wA[1], accA);  accB = ffma2(c0.y, wB[1], accB);
        accC = ffma2(c0.y, wC[1], accC);  accD = ffma2(c0.y, wD[1], accD);
        accA = ffma2(c1.x, wA[2], accA);  accB = ffma2(c1.x, wB[2], accB);
        accC = ffma2(c1.x, wC[2], accC);  accD = ffma2(c1.x, wD[2], accD);
        accA = ffma2(c1.y, wA[3], accA);  accB = ffma2(c1.y, wB[3], accB);
        accC = ffma2(c1.y, wC[3], accC);  accD = ffma2(c1.y, wD[3], accD);

        float sa0, sa1, sb0, sb1, sc0, sc1, sd0, sd1;
        unpack2(accA, sa0, sa1);  unpack2(accB, sb0, sb1);
        unpack2(accC, sc0, sc1);  unpack2(accD, sd0, sd1);
        ull p01 = pack2(sa0 + sa1, sb0 + sb1);    // (c0, c1)
        ull p23 = pack2(sc0 + sc1, sd0 + sd1);    // (c2, c3)
        p01 = fadd2(p01, shfl_xor_u64(p01, 4));
        p23 = fadd2(p23, shfl_xor_u64(p23, 4));
        p01 = fadd2(p01, shfl_xor_u64(p01, 8));
        p23 = fadd2(p23, shfl_xor_u64(p23, 8));
        if (fi == 0) {                             // 4 lanes per edge
            float v0 = __uint_as_float((uint)(meta0 >> 32));
            ull vp = pack2(v0, v0);
            float o0, o1, o2, o3;
            unpack2(fmul2(p01, vp), o0, o1);
            unpack2(fmul2(p23, vp), o2, o3);
            red_add_v4(out + (size_t)((meta0 >> 16) & 0xFFFFu) * C_DIM + cq * 4,
                       o0, o1, o2, o3);
        }
        b0 = b1; b1 = b2;
        meta0 = meta1; meta1 = meta2;
        c0 = n0; c1 = n1;
    }
}

// ---------------------------------------------------------------------------
extern "C" void kernel_launch(void* const* d_in, const int* in_sizes, int n_in,
                              void* d_out, int out_size) {
    const float* features = (const float*)d_in[0];
    const float* vals     = (const float*)d_in[1];
    const float* comps1   = (const float*)d_in[2];
    const float* bases1   = (const float*)d_in[3];
    const float* bias1    = (const float*)d_in[4];
    const float* comps2   = (const float*)d_in[5];
    const float* bases2   = (const float*)d_in[6];
    const float* bias2    = (const float*)d_in[7];
    const int*   rows     = (const int*)d_in[8];
    const int*   cols     = (const int*)d_in[9];
    float*       out      = (float*)d_out;
    const int    nnz      = in_sizes[8];

    // 1. weights + zero hist/done/h1
    compute_w_kernel<<<512, 256>>>(comps1, bases1, comps2, bases2);
    // 2. histogram + last-block scan + out=bias2
    hist_kernel<<<256, 256>>>(rows, nnz, out, bias2);
    // 3. bucket scatter (relation-sorted edge list; g_cursor -> bucket ends)
    scatter_kernel<<<(nnz + SCATTER_CHUNK - 1) / SCATTER_CHUNK, 512>>>(
        rows, cols, vals, nnz);
    // 4. layer 1 (register weights, red.v4 x 8-lane scatter)
    layer1_kernel<<<R_REL * CHUNKS, 256>>>(features);
    // 5. bias + relu
    relu_bias_kernel<<<(N_NODES * E_DIM / 4 + 255) / 256, 256>>>(bias1);
    // 6. layer 2 (red.v4 x 4-lane scatter)
    layer2_kernel<<<R_REL * CHUNKS, 256>>>(out);
}